// round 3
// baseline (speedup 1.0000x reference)
#include <cuda_runtime.h>
#include <cstdint>

#define NB 32
#define H1 224
#define P1 (H1*H1)      // 50176
#define H2 112
#define P2 (H2*H2)      // 12544
#define H3 56
#define P3 (H3*H3)      // 3136

// padded layouts (pads are never written -> stay zero from static init)
#define BXS 228
#define BXR 226
#define H1S 228
#define H1R 225
#define H2S 116
#define H2R 113

// ---------------- scratch ----------------
__device__ uint32_t            g_binx[NB*BXR*BXS];
__device__ uint32_t            g_h1[NB*H1R*H1S];
__device__ unsigned long long  g_h2[NB*H2R*H2S];
__device__ int                 g_cnt[NB*128];
__device__ uint32_t            g_w1[32];
__device__ uint32_t            g_w2[64*9];
__device__ unsigned long long  g_w3[128*9];
__device__ int g_S1[9*32];
__device__ int g_S2[4*64];
__device__ int g_S3[4*128];
__device__ int g_F1[32], g_F2[64], g_F3[128];
__device__ uint32_t g_Finit1, g_Finit2lo, g_Finit2hi;

// -------- integer threshold for sign(BN(a)) with exact fp32 semantics --------
__device__ __forceinline__ void calc_thresh(float g, float bb, float m, float v,
                                            int K, int* T, int* F)
{
    float inv = __fdiv_rn(g, sqrtf(__fadd_rn(v, 1e-5f)));
    float c0  = __fsub_rn(bb, __fmul_rn(m, inv));
    if (inv > 0.f) {
        int A0 = K + 1;
        for (int a = -K; a <= K; a++) {
            float f = __fadd_rn(__fmul_rn((float)a, inv), c0);
            if (f >= 0.f) { A0 = a; break; }
        }
        *T = A0; *F = 0;
    } else if (inv < 0.f) {
        int A1 = -K - 1;
        for (int a = K; a >= -K; a--) {
            float f = __fadd_rn(__fmul_rn((float)a, inv), c0);
            if (f >= 0.f) { A1 = a; break; }
        }
        *T = A1 + 1; *F = 1;
    } else {
        if (c0 < 0.f) { *T =  K + 1;  *F = 0; }
        else          { *T = -(K+1);  *F = 0; }
    }
}

// ---------------- precompute ----------------
__global__ void precompute_kernel(
    const float* w1, const float* w2, const float* w3,
    const float* g1, const float* b1, const float* m1, const float* v1,
    const float* g2, const float* b2, const float* m2, const float* v2,
    const float* g3, const float* b3, const float* m3, const float* v3)
{
    int t = threadIdx.x;
    if (t < 32) {
        uint32_t bits = 0;
        for (int ic = 0; ic < 3; ic++)
            for (int kh = 0; kh < 3; kh++)
                for (int kw = 0; kw < 3; kw++)
                    if (w1[((t*3 + ic)*3 + kh)*3 + kw] < 0.f)
                        bits |= 1u << ((kh*3 + kw)*3 + ic);
        g_w1[t] = bits;
        int T, F; calc_thresh(g1[t], b1[t], m1[t], v1[t], 27, &T, &F);
        g_F1[t] = F;
        for (int bt = 0; bt < 9; bt++) {
            int vt = bt / 3, hz = bt % 3;
            int inv = 0;
            if (vt == 1) inv |= (1|2|4);
            if (vt == 2) inv |= (64|128|256);
            if (hz == 1) inv |= (1|8|64);
            if (hz == 2) inv |= (4|32|256);
            int nv = 27 - 3*__popc(inv);
            int corr = 0;
            for (int tap = 0; tap < 9; tap++)
                if ((inv >> tap) & 1) corr += __popc((bits >> (tap*3)) & 7u);
            g_S1[bt*32 + t] = ((nv - T) >> 1) + corr + 1;
        }
    }
    if (t < 64) {
        uint32_t wt[9];
        for (int tap = 0; tap < 9; tap++) {
            int kh = tap / 3, kw = tap % 3;
            uint32_t bits = 0;
            for (int ic = 0; ic < 32; ic++)
                if (w2[((t*32 + ic)*3 + kh)*3 + kw] < 0.f) bits |= 1u << ic;
            g_w2[t*9 + tap] = bits; wt[tap] = bits;
        }
        int T, F; calc_thresh(g2[t], b2[t], m2[t], v2[t], 288, &T, &F);
        g_F2[t] = F;
        for (int bt = 0; bt < 4; bt++) {
            int inv = 0;
            if (bt & 1) inv |= (1|2|4);
            if (bt & 2) inv |= (1|8|64);
            int nv = 32 * (9 - __popc(inv));
            int corr = 0;
            for (int tap = 0; tap < 9; tap++)
                if ((inv >> tap) & 1) corr += __popc(wt[tap]);
            g_S2[bt*64 + t] = ((nv - T) >> 1) + corr + 1;
        }
    }
    if (t < 128) {
        unsigned long long wt[9];
        for (int tap = 0; tap < 9; tap++) {
            int kh = tap / 3, kw = tap % 3;
            unsigned long long bits = 0;
            for (int ic = 0; ic < 64; ic++)
                if (w3[((t*64 + ic)*3 + kh)*3 + kw] < 0.f) bits |= 1ull << ic;
            g_w3[t*9 + tap] = bits; wt[tap] = bits;
        }
        int T, F; calc_thresh(g3[t], b3[t], m3[t], v3[t], 576, &T, &F);
        g_F3[t] = F;
        for (int bt = 0; bt < 4; bt++) {
            int inv = 0;
            if (bt & 1) inv |= (1|2|4);
            if (bt & 2) inv |= (1|8|64);
            int nv = 64 * (9 - __popc(inv));
            int corr = 0;
            for (int tap = 0; tap < 9; tap++)
                if ((inv >> tap) & 1) corr += __popcll(wt[tap]);
            g_S3[bt*128 + t] = ((nv - T) >> 1) + corr + 1;
        }
    }
    __syncthreads();
    if (t == 0) {
        uint32_t f = 0;
        for (int oc = 0; oc < 32; oc++) f |= ((uint32_t)g_F1[oc]) << oc;
        g_Finit1 = f;
        uint32_t lo = 0, hi = 0;
        for (int oc = 0; oc < 32; oc++) lo |= ((uint32_t)g_F2[oc]) << oc;
        for (int oc = 0; oc < 32; oc++) hi |= ((uint32_t)g_F2[oc+32]) << oc;
        g_Finit2lo = lo; g_Finit2hi = hi;
    }
    for (int j = t; j < NB*128; j += blockDim.x) g_cnt[j] = 0;
}

// ---------------- binarize input into padded layout ----------------
__global__ void binx_kernel(const float* __restrict__ x)
{
    int i = blockIdx.x * blockDim.x + threadIdx.x;
    int b = i / P1, p = i % P1;
    int oh = p / H1, ow = p % H1;
    const float* xb = x + (size_t)b * 3 * P1 + p;
    uint32_t bits = (xb[0]      < 0.f ? 1u : 0u)
                  | (xb[P1]     < 0.f ? 2u : 0u)
                  | (xb[2*P1]   < 0.f ? 4u : 0u);
    g_binx[b*(BXR*BXS) + (oh+1)*BXS + (ow+1)] = bits;
}

// ---------------- layer 1: 3ch -> 32ch, stride 1, 4 px/thread ----------------
__global__ void layer1_kernel()
{
    __shared__ uint32_t sw[32];
    __shared__ int sS[9*32];
    if (threadIdx.x < 32) sw[threadIdx.x] = g_w1[threadIdx.x];
    for (int j = threadIdx.x; j < 9*32; j += blockDim.x) sS[j] = g_S1[j];
    __syncthreads();

    int i = blockIdx.x * blockDim.x + threadIdx.x;   // NB*224*56 exact
    int b = i / 12544, rem = i % 12544;
    int oh = rem / 56, g = rem % 56;
    int ow0 = g * 4;

    const uint32_t* bx = g_binx + b*(BXR*BXS) + oh*BXS + ow0;
    uint32_t c[3][6];
    #pragma unroll
    for (int kh = 0; kh < 3; kh++)
        #pragma unroll
        for (int m = 0; m < 6; m++) c[kh][m] = bx[kh*BXS + m];

    uint32_t xv0 = 0, xv1 = 0, xv2 = 0, xv3 = 0;
    #pragma unroll
    for (int kh = 0; kh < 3; kh++)
        #pragma unroll
        for (int kw = 0; kw < 3; kw++) {
            int sh = (kh*3 + kw)*3;
            xv0 |= c[kh][kw]   << sh;
            xv1 |= c[kh][kw+1] << sh;
            xv2 |= c[kh][kw+2] << sh;
            xv3 |= c[kh][kw+3] << sh;
        }

    int vt = (oh == 0) ? 1 : ((oh == 223) ? 2 : 0);
    const int* Sm = &sS[(vt*3) * 32];
    const int* Sa = &sS[(vt*3 + ((g == 0)  ? 1 : 0)) * 32];
    const int* Sb = &sS[(vt*3 + ((g == 55) ? 2 : 0)) * 32];

    uint32_t fi = g_Finit1;
    uint32_t o0 = fi, o1 = fi, o2 = fi, o3 = fi;
    #pragma unroll
    for (int oc = 0; oc < 32; oc++) {
        uint32_t w = sw[oc];
        uint32_t mb = 1u << oc;
        int srest = Sm[oc];
        if (__popc(xv0 ^ w) >= Sa[oc]) o0 ^= mb;
        if (__popc(xv1 ^ w) >= srest)  o1 ^= mb;
        if (__popc(xv2 ^ w) >= srest)  o2 ^= mb;
        if (__popc(xv3 ^ w) >= Sb[oc]) o3 ^= mb;
    }
    uint32_t* o = g_h1 + b*(H1R*H1S) + (oh+1)*H1S + (ow0+1);
    o[0] = o0; o[1] = o1; o[2] = o2; o[3] = o3;
}

// ---------------- layer 2: 32ch -> 64ch, stride 2, 2 px/thread ----------------
#define L2PIX(CJ, SS, ACC) { \
    int s = __popc(c[0][CJ]^w0)+__popc(c[0][CJ+1]^w1)+__popc(c[0][CJ+2]^w2) \
          + __popc(c[1][CJ]^w3)+__popc(c[1][CJ+1]^w4)+__popc(c[1][CJ+2]^w5) \
          + __popc(c[2][CJ]^w6)+__popc(c[2][CJ+1]^w7)+__popc(c[2][CJ+2]^w8); \
    if (s >= (SS)) (ACC) ^= mb; }

__global__ __launch_bounds__(256) void layer2_kernel()
{
    __shared__ uint32_t sw[64*9];
    __shared__ int sS[4*64];
    for (int j = threadIdx.x; j < 64*9; j += blockDim.x) sw[j] = g_w2[j];
    for (int j = threadIdx.x; j < 4*64; j += blockDim.x) sS[j] = g_S2[j];
    __syncthreads();

    int i = blockIdx.x * blockDim.x + threadIdx.x;   // NB*112*56 = 200704 exact
    int b = i / 6272, rem = i % 6272;
    int oh = rem / 56, g = rem % 56;

    const uint32_t* h1 = g_h1 + b*(H1R*H1S) + (2*oh)*H1S + 4*g;
    uint32_t c[3][5];
    #pragma unroll
    for (int kh = 0; kh < 3; kh++)
        #pragma unroll
        for (int m = 0; m < 5; m++) c[kh][m] = h1[kh*H1S + m];

    int vt = (oh == 0) ? 1 : 0;
    const int* Sm = &sS[vt * 64];
    const int* Sp = &sS[(vt + ((g == 0) ? 2 : 0)) * 64];

    uint32_t l0 = g_Finit2lo, l1 = l0;
    uint32_t h0 = g_Finit2hi, h1r = h0;

    #pragma unroll 8
    for (int oc = 0; oc < 32; oc++) {
        const uint32_t* w = &sw[oc*9];
        uint32_t w0=w[0],w1=w[1],w2=w[2],w3=w[3],w4=w[4],w5=w[5],w6=w[6],w7=w[7],w8=w[8];
        uint32_t mb = 1u << oc;
        L2PIX(0, Sp[oc], l0) L2PIX(2, Sm[oc], l1)
    }
    #pragma unroll 8
    for (int oc = 32; oc < 64; oc++) {
        const uint32_t* w = &sw[oc*9];
        uint32_t w0=w[0],w1=w[1],w2=w[2],w3=w[3],w4=w[4],w5=w[5],w6=w[6],w7=w[7],w8=w[8];
        uint32_t mb = 1u << (oc - 32);
        L2PIX(0, Sp[oc], h0) L2PIX(2, Sm[oc], h1r)
    }
    unsigned long long* o = g_h2 + b*(H2R*H2S) + (oh+1)*H2S + (2*g+1);
    o[0] = ((unsigned long long)h0  << 32) | l0;
    o[1] = ((unsigned long long)h1r << 32) | l1;
}

// ---- layer 3: 64ch -> 128ch, stride 2, 1 px/thread, oc split per warp-half ----
#define L3PIX(CJ) ( \
    __popcll(c[0][CJ]^w0)+__popcll(c[0][CJ+1]^w1)+__popcll(c[0][CJ+2]^w2) \
  + __popcll(c[1][CJ]^w3)+__popcll(c[1][CJ+1]^w4)+__popcll(c[1][CJ+2]^w5) \
  + __popcll(c[2][CJ]^w6)+__popcll(c[2][CJ+1]^w7)+__popcll(c[2][CJ+2]^w8) )

__global__ __launch_bounds__(448) void layer3_kernel()
{
    __shared__ unsigned long long sw[128*9];
    __shared__ int sS[4*128];
    __shared__ int sF[128];
    __shared__ int scnt[128];
    for (int j = threadIdx.x; j < 128*9; j += blockDim.x) sw[j] = g_w3[j];
    for (int j = threadIdx.x; j < 4*128; j += blockDim.x) sS[j] = g_S3[j];
    if (threadIdx.x < 128) { sF[threadIdx.x] = g_F3[threadIdx.x]; scnt[threadIdx.x] = 0; }
    __syncthreads();

    int b = blockIdx.y;
    int wid = threadIdx.x >> 5;          // 0..13
    int lane = threadIdx.x & 31;
    int half = (wid >= 7) ? 1 : 0;       // oc half
    int pgrp = (half ? wid - 7 : wid);   // 0..6
    int p = blockIdx.x * 224 + pgrp * 32 + lane;   // pixel in [0,3136), 14 blk/img
    int oh = p / H3, ow = p % H3;

    const unsigned long long* h2 = g_h2 + b*(H2R*H2S) + (2*oh)*H2S + 2*ow;
    unsigned long long c[3][3];
    #pragma unroll
    for (int kh = 0; kh < 3; kh++)
        #pragma unroll
        for (int m = 0; m < 3; m++) c[kh][m] = h2[kh*H2S + m];

    int vt = (oh == 0) ? 1 : 0;
    int bt = vt + ((ow == 0) ? 2 : 0);
    const int* Sp = &sS[bt * 128];

    int oc0 = half * 64;
    #pragma unroll 4
    for (int k = 0; k < 64; k++) {
        int oc = oc0 + k;
        const unsigned long long* w = &sw[oc*9];
        unsigned long long w0=w[0],w1=w[1],w2=w[2],w3=w[3],w4=w[4],w5=w[5],w6=w[6],w7=w[7],w8=w[8];
        int s = L3PIX(0);
        unsigned bal = __ballot_sync(0xFFFFFFFFu, s >= Sp[oc]);
        if (lane == 0) {
            int cnt = __popc(bal);
            if (sF[oc]) cnt = 32 - cnt;
            atomicAdd(&scnt[oc], cnt);
        }
    }
    __syncthreads();
    if (threadIdx.x < 128)
        atomicAdd(&g_cnt[b*128 + threadIdx.x], scnt[threadIdx.x]);
}

// ---------------- fc ----------------
__global__ void fc_kernel(const float* __restrict__ fcw,
                          const float* __restrict__ fcb,
                          float* __restrict__ out)
{
    int t = threadIdx.x;
    if (t >= NB*2) return;
    int b = t >> 1, k = t & 1;
    float s = fcb[k];
    const float* wr = fcw + k*128;
    for (int c = 0; c < 128; c++) {
        float mean = (float)(P3 - 2*g_cnt[b*128 + c]) / (float)P3;
        s += mean * wr[c];
    }
    out[b*2 + k] = s;
}

// ---------------- launch ----------------
extern "C" void kernel_launch(void* const* d_in, const int* in_sizes, int n_in,
                              void* d_out, int out_size)
{
    const float* x   = (const float*)d_in[0];
    const float* w1  = (const float*)d_in[1];
    const float* w2  = (const float*)d_in[2];
    const float* w3  = (const float*)d_in[3];
    const float* g1  = (const float*)d_in[4];
    const float* b1  = (const float*)d_in[5];
    const float* m1  = (const float*)d_in[6];
    const float* v1  = (const float*)d_in[7];
    const float* g2  = (const float*)d_in[8];
    const float* b2  = (const float*)d_in[9];
    const float* m2  = (const float*)d_in[10];
    const float* v2  = (const float*)d_in[11];
    const float* g3  = (const float*)d_in[12];
    const float* b3  = (const float*)d_in[13];
    const float* m3  = (const float*)d_in[14];
    const float* v3  = (const float*)d_in[15];
    const float* fcw = (const float*)d_in[16];
    const float* fcb = (const float*)d_in[17];
    float* out = (float*)d_out;

    precompute_kernel<<<1, 256>>>(w1, w2, w3,
                                  g1, b1, m1, v1,
                                  g2, b2, m2, v2,
                                  g3, b3, m3, v3);

    binx_kernel<<<(NB*P1)/256, 256>>>(x);          // 6272 blocks
    layer1_kernel<<<(NB*224*56)/256, 256>>>();     // 1568 blocks
    layer2_kernel<<<(NB*112*56)/256, 256>>>();     // 784 blocks, 2px/thread
    dim3 grid3(14, NB);                            // 14 blk/img x 448 thr
    layer3_kernel<<<grid3, 448>>>();
    fc_kernel<<<1, 64>>>(fcw, fcb, out);
}

// round 4
// speedup vs baseline: 1.6098x; 1.6098x over previous
#include <cuda_runtime.h>
#include <cstdint>

#define NB 32
#define H1 224
#define P1 (H1*H1)      // 50176
#define H2 112
#define P2 (H2*H2)      // 12544
#define H3 56
#define P3 (H3*H3)      // 3136

// padded layouts (pads never written -> stay zero)
#define BXS 228
#define BXR 226
#define H1S 228
#define H1R 225
#define H2S 116
#define H2R 113

// ---------------- scratch ----------------
__device__ uint32_t            g_binx[NB*BXR*BXS];
__device__ uint32_t            g_h1[NB*H1R*H1S];
__device__ unsigned long long  g_h2[NB*H2R*H2S];
__device__ int                 g_cnt[NB*128];
__device__ uint32_t            g_w1[32];
__device__ uint32_t            g_w2[64*9];
__device__ unsigned long long  g_w3[128*9];
__device__ int g_S1[9*32];
__device__ int g_S2[4*64];
__device__ int g_S3[4*128];
__device__ int g_F1[32], g_F2[64], g_F3[128];
__device__ uint32_t g_Finit1, g_Finit2lo, g_Finit2hi;

// -------- integer threshold for sign(BN(a)) with exact fp32 semantics --------
__device__ __forceinline__ void calc_thresh(float g, float bb, float m, float v,
                                            int K, int* T, int* F)
{
    float inv = __fdiv_rn(g, sqrtf(__fadd_rn(v, 1e-5f)));
    float c0  = __fsub_rn(bb, __fmul_rn(m, inv));
    if (inv > 0.f) {
        int A0 = K + 1;
        for (int a = -K; a <= K; a++) {
            float f = __fadd_rn(__fmul_rn((float)a, inv), c0);
            if (f >= 0.f) { A0 = a; break; }
        }
        *T = A0; *F = 0;
    } else if (inv < 0.f) {
        int A1 = -K - 1;
        for (int a = K; a >= -K; a--) {
            float f = __fadd_rn(__fmul_rn((float)a, inv), c0);
            if (f >= 0.f) { A1 = a; break; }
        }
        *T = A1 + 1; *F = 1;
    } else {
        if (c0 < 0.f) { *T =  K + 1;  *F = 0; }
        else          { *T = -(K+1);  *F = 0; }
    }
}

// ---------------- precompute ----------------
__global__ void precompute_kernel(
    const float* w1, const float* w2, const float* w3,
    const float* g1, const float* b1, const float* m1, const float* v1,
    const float* g2, const float* b2, const float* m2, const float* v2,
    const float* g3, const float* b3, const float* m3, const float* v3)
{
    int t = threadIdx.x;
    if (t < 32) {
        uint32_t bits = 0;
        for (int ic = 0; ic < 3; ic++)
            for (int kh = 0; kh < 3; kh++)
                for (int kw = 0; kw < 3; kw++)
                    if (w1[((t*3 + ic)*3 + kh)*3 + kw] < 0.f)
                        bits |= 1u << ((kh*3 + kw)*3 + ic);
        g_w1[t] = bits;
        int T, F; calc_thresh(g1[t], b1[t], m1[t], v1[t], 27, &T, &F);
        g_F1[t] = F;
        for (int bt = 0; bt < 9; bt++) {
            int vt = bt / 3, hz = bt % 3;
            int inv = 0;
            if (vt == 1) inv |= (1|2|4);
            if (vt == 2) inv |= (64|128|256);
            if (hz == 1) inv |= (1|8|64);
            if (hz == 2) inv |= (4|32|256);
            int nv = 27 - 3*__popc(inv);
            int corr = 0;
            for (int tap = 0; tap < 9; tap++)
                if ((inv >> tap) & 1) corr += __popc((bits >> (tap*3)) & 7u);
            g_S1[bt*32 + t] = ((nv - T) >> 1) + corr + 1;
        }
    }
    if (t < 64) {
        uint32_t wt[9];
        for (int tap = 0; tap < 9; tap++) {
            int kh = tap / 3, kw = tap % 3;
            uint32_t bits = 0;
            for (int ic = 0; ic < 32; ic++)
                if (w2[((t*32 + ic)*3 + kh)*3 + kw] < 0.f) bits |= 1u << ic;
            g_w2[t*9 + tap] = bits; wt[tap] = bits;
        }
        int T, F; calc_thresh(g2[t], b2[t], m2[t], v2[t], 288, &T, &F);
        g_F2[t] = F;
        for (int bt = 0; bt < 4; bt++) {
            int inv = 0;
            if (bt & 1) inv |= (1|2|4);
            if (bt & 2) inv |= (1|8|64);
            int nv = 32 * (9 - __popc(inv));
            int corr = 0;
            for (int tap = 0; tap < 9; tap++)
                if ((inv >> tap) & 1) corr += __popc(wt[tap]);
            g_S2[bt*64 + t] = ((nv - T) >> 1) + corr + 1;
        }
    }
    if (t < 128) {
        unsigned long long wt[9];
        for (int tap = 0; tap < 9; tap++) {
            int kh = tap / 3, kw = tap % 3;
            unsigned long long bits = 0;
            for (int ic = 0; ic < 64; ic++)
                if (w3[((t*64 + ic)*3 + kh)*3 + kw] < 0.f) bits |= 1ull << ic;
            g_w3[t*9 + tap] = bits; wt[tap] = bits;
        }
        int T, F; calc_thresh(g3[t], b3[t], m3[t], v3[t], 576, &T, &F);
        g_F3[t] = F;
        for (int bt = 0; bt < 4; bt++) {
            int inv = 0;
            if (bt & 1) inv |= (1|2|4);
            if (bt & 2) inv |= (1|8|64);
            int nv = 64 * (9 - __popc(inv));
            int corr = 0;
            for (int tap = 0; tap < 9; tap++)
                if ((inv >> tap) & 1) corr += __popcll(wt[tap]);
            g_S3[bt*128 + t] = ((nv - T) >> 1) + corr + 1;
        }
    }
    __syncthreads();
    if (t == 0) {
        uint32_t f = 0;
        for (int oc = 0; oc < 32; oc++) f |= ((uint32_t)g_F1[oc]) << oc;
        g_Finit1 = f;
        uint32_t lo = 0, hi = 0;
        for (int oc = 0; oc < 32; oc++) lo |= ((uint32_t)g_F2[oc]) << oc;
        for (int oc = 0; oc < 32; oc++) hi |= ((uint32_t)g_F2[oc+32]) << oc;
        g_Finit2lo = lo; g_Finit2hi = hi;
    }
    for (int j = t; j < NB*128; j += blockDim.x) g_cnt[j] = 0;
}

// ---------------- binarize input into padded layout ----------------
__global__ void binx_kernel(const float* __restrict__ x)
{
    int i = blockIdx.x * blockDim.x + threadIdx.x;
    int b = i / P1, p = i % P1;
    int oh = p / H1, ow = p % H1;
    const float* xb = x + (size_t)b * 3 * P1 + p;
    uint32_t bits = (xb[0]      < 0.f ? 1u : 0u)
                  | (xb[P1]     < 0.f ? 2u : 0u)
                  | (xb[2*P1]   < 0.f ? 4u : 0u);
    g_binx[b*(BXR*BXS) + (oh+1)*BXS + (ow+1)] = bits;
}

// ---------------- layer 1: 3ch -> 32ch, stride 1, 2 px/thread ----------------
__global__ __launch_bounds__(256) void layer1_kernel()
{
    __shared__ uint32_t sw[32];
    __shared__ int sS[9*32];
    if (threadIdx.x < 32) sw[threadIdx.x] = g_w1[threadIdx.x];
    for (int j = threadIdx.x; j < 9*32; j += blockDim.x) sS[j] = g_S1[j];
    __syncthreads();

    int i = blockIdx.x * blockDim.x + threadIdx.x;   // NB*224*112 = 802816 exact
    int b = i / 25088, rem = i % 25088;
    int oh = rem / 112, g = rem % 112;
    int ow0 = g * 2;

    const uint32_t* bx = g_binx + b*(BXR*BXS) + oh*BXS + ow0;
    uint32_t c[3][4];
    #pragma unroll
    for (int kh = 0; kh < 3; kh++)
        #pragma unroll
        for (int m = 0; m < 4; m++) c[kh][m] = bx[kh*BXS + m];

    uint32_t xv0 = 0, xv1 = 0;
    #pragma unroll
    for (int kh = 0; kh < 3; kh++)
        #pragma unroll
        for (int kw = 0; kw < 3; kw++) {
            int sh = (kh*3 + kw)*3;
            xv0 |= c[kh][kw]   << sh;
            xv1 |= c[kh][kw+1] << sh;
        }

    int vt = (oh == 0) ? 1 : ((oh == 223) ? 2 : 0);
    const int* Sa = &sS[(vt*3 + ((g == 0)   ? 1 : 0)) * 32];
    const int* Sb = &sS[(vt*3 + ((g == 111) ? 2 : 0)) * 32];

    uint32_t fi = g_Finit1;
    uint32_t o0 = fi, o1 = fi;
    #pragma unroll
    for (int oc = 0; oc < 32; oc++) {
        uint32_t w = sw[oc];
        uint32_t mb = 1u << oc;
        if (__popc(xv0 ^ w) >= Sa[oc]) o0 ^= mb;
        if (__popc(xv1 ^ w) >= Sb[oc]) o1 ^= mb;
    }
    uint32_t* o = g_h1 + b*(H1R*H1S) + (oh+1)*H1S + (ow0+1);
    o[0] = o0; o[1] = o1;
}

// ---------------- layer 2: 32ch -> 64ch, stride 2, 1 px/thread ----------------
__global__ __launch_bounds__(256) void layer2_kernel()
{
    __shared__ uint4 sw4[64*3];   // per oc: (w0..w3)(w4..w7)(w8,-,-,-)
    __shared__ int sS[4*64];
    for (int j = threadIdx.x; j < 64*3; j += blockDim.x) {
        int oc = j / 3, k = j % 3, base = oc*9 + k*4;
        uint4 v;
        v.x = g_w2[base];
        v.y = (k*4 + 1 < 9) ? g_w2[base+1] : 0u;
        v.z = (k*4 + 2 < 9) ? g_w2[base+2] : 0u;
        v.w = (k*4 + 3 < 9) ? g_w2[base+3] : 0u;
        sw4[j] = v;
    }
    for (int j = threadIdx.x; j < 4*64; j += blockDim.x) sS[j] = g_S2[j];
    __syncthreads();

    int i = blockIdx.x * blockDim.x + threadIdx.x;   // NB*P2 = 401408 exact
    int b = i / 12544, rem = i % 12544;
    int oh = rem / 112, ow = rem % 112;

    const uint32_t* h1 = g_h1 + b*(H1R*H1S) + (2*oh)*H1S + 2*ow;
    uint32_t x00 = h1[0],      x01 = h1[1],      x02 = h1[2];
    uint32_t x10 = h1[H1S],    x11 = h1[H1S+1],  x12 = h1[H1S+2];
    uint32_t x20 = h1[2*H1S],  x21 = h1[2*H1S+1], x22 = h1[2*H1S+2];

    int bt = ((oh == 0) ? 1 : 0) + ((ow == 0) ? 2 : 0);
    const int* Sp = &sS[bt * 64];

    uint32_t l0 = g_Finit2lo;
    uint32_t h0 = g_Finit2hi;

    #pragma unroll 8
    for (int oc = 0; oc < 32; oc++) {
        uint4 a = sw4[oc*3], bq = sw4[oc*3+1], cq = sw4[oc*3+2];
        int s = __popc(x00^a.x)+__popc(x01^a.y)+__popc(x02^a.z)
              + __popc(x10^a.w)+__popc(x11^bq.x)+__popc(x12^bq.y)
              + __popc(x20^bq.z)+__popc(x21^bq.w)+__popc(x22^cq.x);
        if (s >= Sp[oc]) l0 ^= 1u << oc;
    }
    #pragma unroll 8
    for (int oc = 32; oc < 64; oc++) {
        uint4 a = sw4[oc*3], bq = sw4[oc*3+1], cq = sw4[oc*3+2];
        int s = __popc(x00^a.x)+__popc(x01^a.y)+__popc(x02^a.z)
              + __popc(x10^a.w)+__popc(x11^bq.x)+__popc(x12^bq.y)
              + __popc(x20^bq.z)+__popc(x21^bq.w)+__popc(x22^cq.x);
        if (s >= Sp[oc]) h0 ^= 1u << (oc - 32);
    }
    g_h2[b*(H2R*H2S) + (oh+1)*H2S + (ow+1)] =
        ((unsigned long long)h0 << 32) | l0;
}

// ---- layer 3: 64ch -> 128ch, stride 2; warp = 32 px, 64 oc (half) ----
__global__ __launch_bounds__(256) void layer3_kernel()
{
    __shared__ ulonglong2 sw2[128*5];  // per oc: (w0,w1)(w2,w3)(w4,w5)(w6,w7)(w8,-)
    __shared__ int sS[4*128];
    for (int j = threadIdx.x; j < 128*5; j += blockDim.x) {
        int oc = j / 5, s2 = j % 5, base = oc*9 + s2*2;
        ulonglong2 v;
        v.x = g_w3[base];
        v.y = (s2*2 + 1 < 9) ? g_w3[base+1] : 0ull;
        sw2[j] = v;
    }
    for (int j = threadIdx.x; j < 4*128; j += blockDim.x) sS[j] = g_S3[j];
    __syncthreads();

    int i = blockIdx.x * blockDim.x + threadIdx.x;   // 784 blocks x 256 = 200704
    int wid = i >> 5, lane = i & 31;
    int half = wid & 1;
    int pw = wid >> 1;              // 0..3135 pixel-warps (98 per image)
    int b = pw / 98;
    int q = (pw % 98) * 32 + lane;  // pixel in [0,3136)
    int oh = q / H3, ow = q % H3;

    const unsigned long long* h2 = g_h2 + b*(H2R*H2S) + (2*oh)*H2S + 2*ow;
    unsigned long long c00 = h2[0],       c01 = h2[1],       c02 = h2[2];
    unsigned long long c10 = h2[H2S],     c11 = h2[H2S+1],   c12 = h2[H2S+2];
    unsigned long long c20 = h2[2*H2S],   c21 = h2[2*H2S+1], c22 = h2[2*H2S+2];

    int bt = ((oh == 0) ? 1 : 0) + ((ow == 0) ? 2 : 0);
    const int* Sp = &sS[bt*128 + half*64];
    const ulonglong2* wbase = &sw2[half*64*5];

    int r0 = 0, r1 = 0;
    #pragma unroll 4
    for (int k = 0; k < 32; k++) {
        const ulonglong2* wp = wbase + k*5;
        ulonglong2 q0 = wp[0], q1 = wp[1], q2 = wp[2], q3 = wp[3], q4 = wp[4];
        int s = __popcll(c00^q0.x)+__popcll(c01^q0.y)+__popcll(c02^q1.x)
              + __popcll(c10^q1.y)+__popcll(c11^q2.x)+__popcll(c12^q2.y)
              + __popcll(c20^q3.x)+__popcll(c21^q3.y)+__popcll(c22^q4.x);
        unsigned bal = __ballot_sync(0xFFFFFFFFu, s >= Sp[k]);
        if (k == lane) r0 = __popc(bal);
    }
    #pragma unroll 4
    for (int k = 32; k < 64; k++) {
        const ulonglong2* wp = wbase + k*5;
        ulonglong2 q0 = wp[0], q1 = wp[1], q2 = wp[2], q3 = wp[3], q4 = wp[4];
        int s = __popcll(c00^q0.x)+__popcll(c01^q0.y)+__popcll(c02^q1.x)
              + __popcll(c10^q1.y)+__popcll(c11^q2.x)+__popcll(c12^q2.y)
              + __popcll(c20^q3.x)+__popcll(c21^q3.y)+__popcll(c22^q4.x);
        unsigned bal = __ballot_sync(0xFFFFFFFFu, s >= Sp[k]);
        if (k - 32 == lane) r1 = __popc(bal);
    }

    int oc0 = half*64 + lane;     // lane owns oc0 (count r0) and oc0+32 (r1)
    int oc1 = oc0 + 32;
    if (g_F3[oc0]) r0 = 32 - r0;
    if (g_F3[oc1]) r1 = 32 - r1;
    atomicAdd(&g_cnt[b*128 + oc0], r0);
    atomicAdd(&g_cnt[b*128 + oc1], r1);
}

// ---------------- fc ----------------
__global__ void fc_kernel(const float* __restrict__ fcw,
                          const float* __restrict__ fcb,
                          float* __restrict__ out)
{
    int t = threadIdx.x;
    if (t >= NB*2) return;
    int b = t >> 1, k = t & 1;
    float s = fcb[k];
    const float* wr = fcw + k*128;
    for (int c = 0; c < 128; c++) {
        float mean = (float)(P3 - 2*g_cnt[b*128 + c]) / (float)P3;
        s += mean * wr[c];
    }
    out[b*2 + k] = s;
}

// ---------------- launch ----------------
extern "C" void kernel_launch(void* const* d_in, const int* in_sizes, int n_in,
                              void* d_out, int out_size)
{
    const float* x   = (const float*)d_in[0];
    const float* w1  = (const float*)d_in[1];
    const float* w2  = (const float*)d_in[2];
    const float* w3  = (const float*)d_in[3];
    const float* g1  = (const float*)d_in[4];
    const float* b1  = (const float*)d_in[5];
    const float* m1  = (const float*)d_in[6];
    const float* v1  = (const float*)d_in[7];
    const float* g2  = (const float*)d_in[8];
    const float* b2  = (const float*)d_in[9];
    const float* m2  = (const float*)d_in[10];
    const float* v2  = (const float*)d_in[11];
    const float* g3  = (const float*)d_in[12];
    const float* b3  = (const float*)d_in[13];
    const float* m3  = (const float*)d_in[14];
    const float* v3  = (const float*)d_in[15];
    const float* fcw = (const float*)d_in[16];
    const float* fcb = (const float*)d_in[17];
    float* out = (float*)d_out;

    precompute_kernel<<<1, 256>>>(w1, w2, w3,
                                  g1, b1, m1, v1,
                                  g2, b2, m2, v2,
                                  g3, b3, m3, v3);

    binx_kernel<<<(NB*P1)/256, 256>>>(x);            // 6272 blocks
    layer1_kernel<<<(NB*224*112)/256, 256>>>();      // 3136 blocks, 2px/thr
    layer2_kernel<<<(NB*P2)/256, 256>>>();           // 1568 blocks, 1px/thr
    layer3_kernel<<<(NB*P3*2)/256, 256>>>();         // 784 blocks
    fc_kernel<<<1, 64>>>(fcw, fcb, out);
}

// round 5
// speedup vs baseline: 1.7202x; 1.0686x over previous
#include <cuda_runtime.h>
#include <cstdint>

#define NB 32
#define H1 224
#define P1 (H1*H1)      // 50176
#define H2 112
#define P2 (H2*H2)      // 12544
#define H3 56
#define P3 (H3*H3)      // 3136

// padded layouts (pads never written -> stay zero)
#define BXS 228
#define BXR 226
#define H1S 228
#define H1R 225
#define H2S 116
#define H2R 113

#define MAJ(a,b,c) (((a)&(b)) | ((a)&(c)) | ((b)&(c)))

// ---------------- scratch ----------------
__device__ uint32_t            g_binx[NB*BXR*BXS];
__device__ uint32_t            g_h1[NB*H1R*H1S];
__device__ unsigned long long  g_h2[NB*H2R*H2S];
__device__ int                 g_cnt[NB*128];
__device__ uint32_t            g_w1[32];
__device__ uint32_t            g_w2[64*9];
__device__ unsigned long long  g_w3[128*9];
__device__ int g_S1[9*32];
__device__ int g_S2[4*64];
__device__ int g_S3[4*128];
__device__ int g_F1[32], g_F2[64], g_F3[128];
__device__ uint32_t g_Finit1, g_Finit2lo, g_Finit2hi;

// -------- integer threshold for sign(BN(a)) with exact fp32 semantics --------
__device__ __forceinline__ void calc_thresh(float g, float bb, float m, float v,
                                            int K, int* T, int* F)
{
    float inv = __fdiv_rn(g, sqrtf(__fadd_rn(v, 1e-5f)));
    float c0  = __fsub_rn(bb, __fmul_rn(m, inv));
    if (inv > 0.f) {
        int A0 = K + 1;
        for (int a = -K; a <= K; a++) {
            float f = __fadd_rn(__fmul_rn((float)a, inv), c0);
            if (f >= 0.f) { A0 = a; break; }
        }
        *T = A0; *F = 0;
    } else if (inv < 0.f) {
        int A1 = -K - 1;
        for (int a = K; a >= -K; a--) {
            float f = __fadd_rn(__fmul_rn((float)a, inv), c0);
            if (f >= 0.f) { A1 = a; break; }
        }
        *T = A1 + 1; *F = 1;
    } else {
        if (c0 < 0.f) { *T =  K + 1;  *F = 0; }
        else          { *T = -(K+1);  *F = 0; }
    }
}

// ---------------- precompute ----------------
__global__ void precompute_kernel(
    const float* w1, const float* w2, const float* w3,
    const float* g1, const float* b1, const float* m1, const float* v1,
    const float* g2, const float* b2, const float* m2, const float* v2,
    const float* g3, const float* b3, const float* m3, const float* v3)
{
    int t = threadIdx.x;
    if (t < 32) {
        uint32_t bits = 0;
        for (int ic = 0; ic < 3; ic++)
            for (int kh = 0; kh < 3; kh++)
                for (int kw = 0; kw < 3; kw++)
                    if (w1[((t*3 + ic)*3 + kh)*3 + kw] < 0.f)
                        bits |= 1u << ((kh*3 + kw)*3 + ic);
        g_w1[t] = bits;
        int T, F; calc_thresh(g1[t], b1[t], m1[t], v1[t], 27, &T, &F);
        g_F1[t] = F;
        for (int bt = 0; bt < 9; bt++) {
            int vt = bt / 3, hz = bt % 3;
            int inv = 0;
            if (vt == 1) inv |= (1|2|4);
            if (vt == 2) inv |= (64|128|256);
            if (hz == 1) inv |= (1|8|64);
            if (hz == 2) inv |= (4|32|256);
            int nv = 27 - 3*__popc(inv);
            int corr = 0;
            for (int tap = 0; tap < 9; tap++)
                if ((inv >> tap) & 1) corr += __popc((bits >> (tap*3)) & 7u);
            g_S1[bt*32 + t] = ((nv - T) >> 1) + corr + 1;
        }
    }
    if (t < 64) {
        uint32_t wt[9];
        for (int tap = 0; tap < 9; tap++) {
            int kh = tap / 3, kw = tap % 3;
            uint32_t bits = 0;
            for (int ic = 0; ic < 32; ic++)
                if (w2[((t*32 + ic)*3 + kh)*3 + kw] < 0.f) bits |= 1u << ic;
            g_w2[t*9 + tap] = bits; wt[tap] = bits;
        }
        int T, F; calc_thresh(g2[t], b2[t], m2[t], v2[t], 288, &T, &F);
        g_F2[t] = F;
        for (int bt = 0; bt < 4; bt++) {
            int inv = 0;
            if (bt & 1) inv |= (1|2|4);
            if (bt & 2) inv |= (1|8|64);
            int nv = 32 * (9 - __popc(inv));
            int corr = 0;
            for (int tap = 0; tap < 9; tap++)
                if ((inv >> tap) & 1) corr += __popc(wt[tap]);
            g_S2[bt*64 + t] = ((nv - T) >> 1) + corr + 1;
        }
    }
    if (t < 128) {
        unsigned long long wt[9];
        for (int tap = 0; tap < 9; tap++) {
            int kh = tap / 3, kw = tap % 3;
            unsigned long long bits = 0;
            for (int ic = 0; ic < 64; ic++)
                if (w3[((t*64 + ic)*3 + kh)*3 + kw] < 0.f) bits |= 1ull << ic;
            g_w3[t*9 + tap] = bits; wt[tap] = bits;
        }
        int T, F; calc_thresh(g3[t], b3[t], m3[t], v3[t], 576, &T, &F);
        g_F3[t] = F;
        for (int bt = 0; bt < 4; bt++) {
            int inv = 0;
            if (bt & 1) inv |= (1|2|4);
            if (bt & 2) inv |= (1|8|64);
            int nv = 64 * (9 - __popc(inv));
            int corr = 0;
            for (int tap = 0; tap < 9; tap++)
                if ((inv >> tap) & 1) corr += __popcll(wt[tap]);
            g_S3[bt*128 + t] = ((nv - T) >> 1) + corr + 1;
        }
    }
    __syncthreads();
    if (t == 0) {
        uint32_t f = 0;
        for (int oc = 0; oc < 32; oc++) f |= ((uint32_t)g_F1[oc]) << oc;
        g_Finit1 = f;
        uint32_t lo = 0, hi = 0;
        for (int oc = 0; oc < 32; oc++) lo |= ((uint32_t)g_F2[oc]) << oc;
        for (int oc = 0; oc < 32; oc++) hi |= ((uint32_t)g_F2[oc+32]) << oc;
        g_Finit2lo = lo; g_Finit2hi = hi;
    }
    for (int j = t; j < NB*128; j += blockDim.x) g_cnt[j] = 0;
}

// ---------------- binarize input into padded layout ----------------
__global__ void binx_kernel(const float* __restrict__ x)
{
    int i = blockIdx.x * blockDim.x + threadIdx.x;
    int b = i / P1, p = i % P1;
    int oh = p / H1, ow = p % H1;
    const float* xb = x + (size_t)b * 3 * P1 + p;
    uint32_t bits = (xb[0]      < 0.f ? 1u : 0u)
                  | (xb[P1]     < 0.f ? 2u : 0u)
                  | (xb[2*P1]   < 0.f ? 4u : 0u);
    g_binx[b*(BXR*BXS) + (oh+1)*BXS + (ow+1)] = bits;
}

// ---------------- layer 1: 3ch -> 32ch, stride 1, 2 px/thread ----------------
__global__ __launch_bounds__(256) void layer1_kernel()
{
    __shared__ uint32_t sw[32];
    __shared__ int sS[9*32];
    if (threadIdx.x < 32) sw[threadIdx.x] = g_w1[threadIdx.x];
    for (int j = threadIdx.x; j < 9*32; j += blockDim.x) sS[j] = g_S1[j];
    __syncthreads();

    int i = blockIdx.x * blockDim.x + threadIdx.x;   // NB*224*112 = 802816 exact
    int b = i / 25088, rem = i % 25088;
    int oh = rem / 112, g = rem % 112;
    int ow0 = g * 2;

    const uint32_t* bx = g_binx + b*(BXR*BXS) + oh*BXS + ow0;
    uint32_t c[3][4];
    #pragma unroll
    for (int kh = 0; kh < 3; kh++)
        #pragma unroll
        for (int m = 0; m < 4; m++) c[kh][m] = bx[kh*BXS + m];

    uint32_t xv0 = 0, xv1 = 0;
    #pragma unroll
    for (int kh = 0; kh < 3; kh++)
        #pragma unroll
        for (int kw = 0; kw < 3; kw++) {
            int sh = (kh*3 + kw)*3;
            xv0 |= c[kh][kw]   << sh;
            xv1 |= c[kh][kw+1] << sh;
        }

    int vt = (oh == 0) ? 1 : ((oh == 223) ? 2 : 0);
    const int* Sa = &sS[(vt*3 + ((g == 0)   ? 1 : 0)) * 32];
    const int* Sb = &sS[(vt*3 + ((g == 111) ? 2 : 0)) * 32];

    uint32_t fi = g_Finit1;
    uint32_t o0 = fi, o1 = fi;
    #pragma unroll
    for (int oc = 0; oc < 32; oc++) {
        uint32_t w = sw[oc];
        uint32_t mb = 1u << oc;
        if (__popc(xv0 ^ w) >= Sa[oc]) o0 ^= mb;
        if (__popc(xv1 ^ w) >= Sb[oc]) o1 ^= mb;
    }
    uint32_t* o = g_h1 + b*(H1R*H1S) + (oh+1)*H1S + (ow0+1);
    o[0] = o0; o[1] = o1;
}

// ---------------- layer 2: 32ch -> 64ch, stride 2, 1 px/thread, CSA popcount --
__global__ __launch_bounds__(256) void layer2_kernel()
{
    __shared__ uint4 sw4[64*3];   // per oc: (w0..w3)(w4..w7)(w8,-,-,-)
    __shared__ int sS[4*64];
    for (int j = threadIdx.x; j < 64*3; j += blockDim.x) {
        int oc = j / 3, k = j % 3, base = oc*9 + k*4;
        uint4 v;
        v.x = g_w2[base];
        v.y = (k*4 + 1 < 9) ? g_w2[base+1] : 0u;
        v.z = (k*4 + 2 < 9) ? g_w2[base+2] : 0u;
        v.w = (k*4 + 3 < 9) ? g_w2[base+3] : 0u;
        sw4[j] = v;
    }
    for (int j = threadIdx.x; j < 4*64; j += blockDim.x) sS[j] = g_S2[j];
    __syncthreads();

    int i = blockIdx.x * blockDim.x + threadIdx.x;   // NB*P2 = 401408 exact
    int b = i / 12544, rem = i % 12544;
    int oh = rem / 112, ow = rem % 112;

    const uint32_t* h1 = g_h1 + b*(H1R*H1S) + (2*oh)*H1S + 2*ow;
    uint32_t x00 = h1[0],      x01 = h1[1],      x02 = h1[2];
    uint32_t x10 = h1[H1S],    x11 = h1[H1S+1],  x12 = h1[H1S+2];
    uint32_t x20 = h1[2*H1S],  x21 = h1[2*H1S+1], x22 = h1[2*H1S+2];

    int bt = ((oh == 0) ? 1 : 0) + ((ow == 0) ? 2 : 0);
    const int* Sp = &sS[bt * 64];

    uint32_t l0 = g_Finit2lo;
    uint32_t h0 = g_Finit2hi;

    #pragma unroll 8
    for (int oc = 0; oc < 32; oc++) {
        uint4 a = sw4[oc*3], bq = sw4[oc*3+1], cq = sw4[oc*3+2];
        uint32_t t0 = x00^a.x,  t1 = x01^a.y,  t2 = x02^a.z;
        uint32_t t3 = x10^a.w,  t4 = x11^bq.x, t5 = x12^bq.y;
        uint32_t t6 = x20^bq.z, t7 = x21^bq.w, t8 = x22^cq.x;
        uint32_t s0 = t0^t1^t2, k0 = MAJ(t0,t1,t2);
        uint32_t s1 = t3^t4^t5, k1 = MAJ(t3,t4,t5);
        uint32_t s2 = t6^t7^t8, k2 = MAJ(t6,t7,t8);
        uint32_t s3 = s0^s1^s2, k3 = MAJ(s0,s1,s2);
        uint32_t s4 = k0^k1^k2, k4 = MAJ(k0,k1,k2);
        int tot = __popc(s3) + ((__popc(k3) + __popc(s4)) << 1)
                + (__popc(k4) << 2);
        if (tot >= Sp[oc]) l0 ^= 1u << oc;
    }
    #pragma unroll 8
    for (int oc = 32; oc < 64; oc++) {
        uint4 a = sw4[oc*3], bq = sw4[oc*3+1], cq = sw4[oc*3+2];
        uint32_t t0 = x00^a.x,  t1 = x01^a.y,  t2 = x02^a.z;
        uint32_t t3 = x10^a.w,  t4 = x11^bq.x, t5 = x12^bq.y;
        uint32_t t6 = x20^bq.z, t7 = x21^bq.w, t8 = x22^cq.x;
        uint32_t s0 = t0^t1^t2, k0 = MAJ(t0,t1,t2);
        uint32_t s1 = t3^t4^t5, k1 = MAJ(t3,t4,t5);
        uint32_t s2 = t6^t7^t8, k2 = MAJ(t6,t7,t8);
        uint32_t s3 = s0^s1^s2, k3 = MAJ(s0,s1,s2);
        uint32_t s4 = k0^k1^k2, k4 = MAJ(k0,k1,k2);
        int tot = __popc(s3) + ((__popc(k3) + __popc(s4)) << 1)
                + (__popc(k4) << 2);
        if (tot >= Sp[oc]) h0 ^= 1u << (oc - 32);
    }
    g_h2[b*(H2R*H2S) + (oh+1)*H2S + (ow+1)] =
        ((unsigned long long)h0 << 32) | l0;
}

// ---- layer 3: 64ch -> 128ch; warp = 32 px, 64 oc (half); CSA popcount ----
__global__ __launch_bounds__(256) void layer3_kernel()
{
    __shared__ ulonglong2 sw2[128*5];  // per oc: (w0,w1)(w2,w3)(w4,w5)(w6,w7)(w8,-)
    __shared__ int sS[4*128];
    for (int j = threadIdx.x; j < 128*5; j += blockDim.x) {
        int oc = j / 5, s2 = j % 5, base = oc*9 + s2*2;
        ulonglong2 v;
        v.x = g_w3[base];
        v.y = (s2*2 + 1 < 9) ? g_w3[base+1] : 0ull;
        sw2[j] = v;
    }
    for (int j = threadIdx.x; j < 4*128; j += blockDim.x) sS[j] = g_S3[j];
    __syncthreads();

    int i = blockIdx.x * blockDim.x + threadIdx.x;   // 784 blocks x 256
    int wid = i >> 5, lane = i & 31;
    int half = wid & 1;
    int pw = wid >> 1;              // 0..3135 pixel-warps (98 per image)
    int b = pw / 98;
    int q = (pw % 98) * 32 + lane;  // pixel in [0,3136)
    int oh = q / H3, ow = q % H3;

    const unsigned long long* h2 = g_h2 + b*(H2R*H2S) + (2*oh)*H2S + 2*ow;
    unsigned long long c00 = h2[0],       c01 = h2[1],       c02 = h2[2];
    unsigned long long c10 = h2[H2S],     c11 = h2[H2S+1],   c12 = h2[H2S+2];
    unsigned long long c20 = h2[2*H2S],   c21 = h2[2*H2S+1], c22 = h2[2*H2S+2];

    int bt = ((oh == 0) ? 1 : 0) + ((ow == 0) ? 2 : 0);
    const int* Sp = &sS[bt*128 + half*64];
    const ulonglong2* wbase = &sw2[half*64*5];

    int r0 = 0, r1 = 0;
    #pragma unroll 4
    for (int k = 0; k < 64; k++) {
        const ulonglong2* wp = wbase + k*5;
        ulonglong2 q0 = wp[0], q1 = wp[1], q2 = wp[2], q3 = wp[3], q4 = wp[4];
        unsigned long long t0 = c00^q0.x, t1 = c01^q0.y, t2 = c02^q1.x;
        unsigned long long t3 = c10^q1.y, t4 = c11^q2.x, t5 = c12^q2.y;
        unsigned long long t6 = c20^q3.x, t7 = c21^q3.y, t8 = c22^q4.x;
        unsigned long long s0 = t0^t1^t2, k0 = MAJ(t0,t1,t2);
        unsigned long long s1 = t3^t4^t5, k1 = MAJ(t3,t4,t5);
        unsigned long long s2 = t6^t7^t8, k2 = MAJ(t6,t7,t8);
        unsigned long long s3 = s0^s1^s2, k3 = MAJ(s0,s1,s2);
        unsigned long long s4 = k0^k1^k2, k4 = MAJ(k0,k1,k2);
        int tot = __popcll(s3) + ((__popcll(k3) + __popcll(s4)) << 1)
                + (__popcll(k4) << 2);
        unsigned bal = __ballot_sync(0xFFFFFFFFu, tot >= Sp[k]);
        if ((k & 31) == lane) { if (k < 32) r0 = __popc(bal); else r1 = __popc(bal); }
    }

    int oc0 = half*64 + lane;     // lane owns oc0 (r0) and oc0+32 (r1)
    int oc1 = oc0 + 32;
    if (g_F3[oc0]) r0 = 32 - r0;
    if (g_F3[oc1]) r1 = 32 - r1;
    atomicAdd(&g_cnt[b*128 + oc0], r0);
    atomicAdd(&g_cnt[b*128 + oc1], r1);
}

// ---------------- fc ----------------
__global__ void fc_kernel(const float* __restrict__ fcw,
                          const float* __restrict__ fcb,
                          float* __restrict__ out)
{
    int t = threadIdx.x;
    if (t >= NB*2) return;
    int b = t >> 1, k = t & 1;
    float s = fcb[k];
    const float* wr = fcw + k*128;
    for (int c = 0; c < 128; c++) {
        float mean = (float)(P3 - 2*g_cnt[b*128 + c]) / (float)P3;
        s += mean * wr[c];
    }
    out[b*2 + k] = s;
}

// ---------------- launch ----------------
extern "C" void kernel_launch(void* const* d_in, const int* in_sizes, int n_in,
                              void* d_out, int out_size)
{
    const float* x   = (const float*)d_in[0];
    const float* w1  = (const float*)d_in[1];
    const float* w2  = (const float*)d_in[2];
    const float* w3  = (const float*)d_in[3];
    const float* g1  = (const float*)d_in[4];
    const float* b1  = (const float*)d_in[5];
    const float* m1  = (const float*)d_in[6];
    const float* v1  = (const float*)d_in[7];
    const float* g2  = (const float*)d_in[8];
    const float* b2  = (const float*)d_in[9];
    const float* m2  = (const float*)d_in[10];
    const float* v2  = (const float*)d_in[11];
    const float* g3  = (const float*)d_in[12];
    const float* b3  = (const float*)d_in[13];
    const float* m3  = (const float*)d_in[14];
    const float* v3  = (const float*)d_in[15];
    const float* fcw = (const float*)d_in[16];
    const float* fcb = (const float*)d_in[17];
    float* out = (float*)d_out;

    precompute_kernel<<<1, 256>>>(w1, w2, w3,
                                  g1, b1, m1, v1,
                                  g2, b2, m2, v2,
                                  g3, b3, m3, v3);

    binx_kernel<<<(NB*P1)/256, 256>>>(x);            // 6272 blocks
    layer1_kernel<<<(NB*224*112)/256, 256>>>();      // 3136 blocks, 2px/thr
    layer2_kernel<<<(NB*P2)/256, 256>>>();           // 1568 blocks, 1px/thr
    layer3_kernel<<<(NB*P3*2)/256, 256>>>();         // 784 blocks
    fc_kernel<<<1, 64>>>(fcw, fcb, out);
}